// round 9
// baseline (speedup 1.0000x reference)
#include <cuda_runtime.h>
#include <cstdint>

// Problem constants
#define MAXN 100000
#define MAXE 3200000
#define FDIM 7
#define HDIM 128
#define DDIM 64
#define EPSV 1e-5f

typedef unsigned long long ull;

// Scratch (__device__ globals; allocation-free rule)
__device__ float g_bufA[MAXN * HDIM];   // running node features h [N,128]
__device__ float g_bufB[MAXN * HDIM];   // h @ W (stride = DO of current layer)
__device__ float g_dinv[MAXN];
__device__ int   g_rowptr[MAXN + 1];    // CSR row pointers over dst
__device__ int   g_fill[MAXN];          // scatter cursors
__device__ int2  g_edge[MAXE];          // CSR: (src, coef-as-int) per incoming edge

// ---- Blackwell packed-f32x2 helpers --------------------------------------
__device__ __forceinline__ ull pack2(float lo, float hi) {
    ull r; asm("mov.b64 %0, {%1, %2};" : "=l"(r) : "f"(lo), "f"(hi)); return r;
}
__device__ __forceinline__ void fma2(ull& d, ull a, ull b) {
    asm("fma.rn.f32x2 %0, %1, %2, %3;" : "=l"(d) : "l"(a), "l"(b), "l"(d));
}
__device__ __forceinline__ float2 unpack2(ull v) {
    float2 f; asm("mov.b64 {%0, %1}, %2;" : "=f"(f.x), "=f"(f.y) : "l"(v)); return f;
}

// ---------------------------------------------------------------------------
// CSR build  (edge_index is INT32: row 0 = src[0..E), row 1 = dst[0..E))
// ---------------------------------------------------------------------------
__global__ void zero_rowptr_kernel(int n1) {
    int i = blockIdx.x * blockDim.x + threadIdx.x;
    if (i < n1) g_rowptr[i] = 0;
}

__global__ void hist_kernel(const int* __restrict__ ei, int E_) {
    int e = blockIdx.x * blockDim.x + threadIdx.x;
    if (e < E_) {
        int dst = ei[E_ + e];
        atomicAdd(&g_rowptr[dst + 1], 1);   // INT atomic only
    }
}

// in-place inclusive scan over rowptr[0..n) — one block, 1024 threads
__global__ void scan_kernel(int n) {
    __shared__ int part[1024];
    int t = threadIdx.x;
    int C = (n + 1023) / 1024;
    int b = t * C;
    int e = b + C; if (e > n) e = n;
    int s = 0;
    for (int i = b; i < e; i++) s += g_rowptr[i];
    part[t] = s;
    __syncthreads();
    if (t == 0) {
        int run = 0;
        for (int i = 0; i < 1024; i++) { int x = part[i]; part[i] = run; run += x; }
    }
    __syncthreads();
    int run = part[t];
    for (int i = b; i < e; i++) { run += g_rowptr[i]; g_rowptr[i] = run; }
}

// dinv from degrees (+1 self-loop); also init fill cursors
__global__ void dinv_fill_kernel(int n) {
    int i = blockIdx.x * blockDim.x + threadIdx.x;
    if (i < n) {
        int beg = g_rowptr[i];
        int deg = g_rowptr[i + 1] - beg;
        g_dinv[i] = rsqrtf((float)deg + 1.0f);
        g_fill[i] = beg;
    }
}

__global__ void scatter_kernel(const int* __restrict__ ei, int E_) {
    int e = blockIdx.x * blockDim.x + threadIdx.x;
    if (e < E_) {
        int src = ei[e];
        int dst = ei[E_ + e];
        int pos = atomicAdd(&g_fill[dst], 1);   // INT atomic
        float coef = g_dinv[src] * g_dinv[dst];
        g_edge[pos] = make_int2(src, __float_as_int(coef));
    }
}

// ---------------------------------------------------------------------------
// input projection: bufA = relu(x @ W_in + b_in)   x:[N,7] W:[7,128]
// ---------------------------------------------------------------------------
__global__ void inproj_kernel(const float* __restrict__ x,
                              const float* __restrict__ W,
                              const float* __restrict__ b,
                              int n) {
    int i = blockIdx.x * blockDim.x + threadIdx.x;
    if (i >= n * HDIM) return;
    int node = i >> 7;
    int c = i & 127;
    float s = b[c];
#pragma unroll
    for (int k = 0; k < FDIM; k++)
        s = fmaf(x[node * FDIM + k], W[k * HDIM + c], s);
    g_bufA[i] = fmaxf(s, 0.0f);
}

// ---------------------------------------------------------------------------
// GEMM: bufB = bufA @ W   A:[n,128], W:[128,DO], bufB stride DO
// 64 rows x DO cols per block, 256 threads. Packed f32x2 FMA inner loop;
// A tile read from smem as LDS.128 along k (warp-broadcast, conflict-free).
// ---------------------------------------------------------------------------
template <int DO>
__global__ void gemm_kernel(const float* __restrict__ W, int n) {
    constexpr int DI = HDIM;
    constexpr int TM = 64;
    constexpr int CT = DO / 4;        // threads along columns (float4)
    constexpr int RT = 256 / CT;      // threads along rows
    constexpr int RM = TM / RT;       // rows per thread
    constexpr int LDA = DI + 4;       // pad keeps rows 16B-aligned (528 B stride)

    __shared__ float Asm[TM * LDA];

    int m0 = blockIdx.x * TM;
    int tid = threadIdx.x;

    // cooperative float4 tile load (coalesced gmem, conflict-free STS.128)
    {
        const float4* src4 = reinterpret_cast<const float4*>(g_bufA);
        for (int idx = tid; idx < TM * (DI / 4); idx += 256) {
            int r = idx >> 5;                 // DI/4 = 32
            int c4 = idx & 31;
            int gr = m0 + r;
            float4 vv = (gr < n) ? src4[(size_t)gr * (DI / 4) + c4]
                                 : make_float4(0.f, 0.f, 0.f, 0.f);
            *reinterpret_cast<float4*>(&Asm[r * LDA + c4 * 4]) = vv;
        }
    }
    __syncthreads();

    int ct = tid % CT;
    int ry = tid / CT;
    int c0 = ct * 4;

    ull acc01[RM], acc23[RM];
#pragma unroll
    for (int j = 0; j < RM; j++) { acc01[j] = pack2(0.f, 0.f); acc23[j] = pack2(0.f, 0.f); }

    for (int k = 0; k < DI; k += 4) {
        ull w01[4], w23[4];
#pragma unroll
        for (int kk = 0; kk < 4; kk++) {
            float4 wv = *reinterpret_cast<const float4*>(&W[(k + kk) * DO + c0]);
            w01[kk] = pack2(wv.x, wv.y);
            w23[kk] = pack2(wv.z, wv.w);
        }
#pragma unroll
        for (int j = 0; j < RM; j++) {
            float4 av = *reinterpret_cast<const float4*>(&Asm[(ry + RT * j) * LDA + k]);
            ull a;
            a = pack2(av.x, av.x); fma2(acc01[j], a, w01[0]); fma2(acc23[j], a, w23[0]);
            a = pack2(av.y, av.y); fma2(acc01[j], a, w01[1]); fma2(acc23[j], a, w23[1]);
            a = pack2(av.z, av.z); fma2(acc01[j], a, w01[2]); fma2(acc23[j], a, w23[2]);
            a = pack2(av.w, av.w); fma2(acc01[j], a, w01[3]); fma2(acc23[j], a, w23[3]);
        }
    }

#pragma unroll
    for (int j = 0; j < RM; j++) {
        int node = m0 + ry + RT * j;
        if (node < n) {
            float2 lo = unpack2(acc01[j]);
            float2 hi = unpack2(acc23[j]);
            float4 o; o.x = lo.x; o.y = lo.y; o.z = hi.x; o.w = hi.y;
            *reinterpret_cast<float4*>(&g_bufB[(size_t)node * DO + c0]) = o;
        }
    }
}

// ---------------------------------------------------------------------------
// Fused gather: agg = sum_in coef*bufB[src] + bufB[node]*dinv^2 + bias,
// then BN (+relu+residual for hidden layers). One lane per (node, 4 cols).
// NO atomics, NO float reds. Edge (src,coef) packed in one int2 load.
// ---------------------------------------------------------------------------
template <int DO, bool FINAL>
__global__ void gather_kernel(const float* __restrict__ bias,
                              const float* __restrict__ g,
                              const float* __restrict__ be,
                              const float* __restrict__ m,
                              const float* __restrict__ v,
                              float* __restrict__ out,
                              int n) {
    constexpr int LPN = DO / 4;       // lanes per node
    int gt = blockIdx.x * blockDim.x + threadIdx.x;
    int node = gt / LPN;
    int c = gt - node * LPN;
    if (node >= n) return;
    int c0 = c * 4;

    const float4* Bv = reinterpret_cast<const float4*>(g_bufB);

    float dv = g_dinv[node];
    float d2 = dv * dv;

    float4 hv = Bv[(size_t)node * LPN + c];
    float4 acc;
    acc.x = fmaf(hv.x, d2, bias[c0 + 0]);
    acc.y = fmaf(hv.y, d2, bias[c0 + 1]);
    acc.z = fmaf(hv.z, d2, bias[c0 + 2]);
    acc.w = fmaf(hv.w, d2, bias[c0 + 3]);

    int j = g_rowptr[node];
    int end = g_rowptr[node + 1];

    // unroll-by-4 for MLP against L2 latency
    for (; j + 4 <= end; j += 4) {
        int2 e0 = g_edge[j + 0], e1 = g_edge[j + 1];
        int2 e2 = g_edge[j + 2], e3 = g_edge[j + 3];
        float k0 = __int_as_float(e0.y), k1 = __int_as_float(e1.y);
        float k2 = __int_as_float(e2.y), k3 = __int_as_float(e3.y);
        float4 v0 = Bv[(size_t)e0.x * LPN + c];
        float4 v1 = Bv[(size_t)e1.x * LPN + c];
        float4 v2 = Bv[(size_t)e2.x * LPN + c];
        float4 v3 = Bv[(size_t)e3.x * LPN + c];
        acc.x = fmaf(k0, v0.x, acc.x); acc.y = fmaf(k0, v0.y, acc.y);
        acc.z = fmaf(k0, v0.z, acc.z); acc.w = fmaf(k0, v0.w, acc.w);
        acc.x = fmaf(k1, v1.x, acc.x); acc.y = fmaf(k1, v1.y, acc.y);
        acc.z = fmaf(k1, v1.z, acc.z); acc.w = fmaf(k1, v1.w, acc.w);
        acc.x = fmaf(k2, v2.x, acc.x); acc.y = fmaf(k2, v2.y, acc.y);
        acc.z = fmaf(k2, v2.z, acc.z); acc.w = fmaf(k2, v2.w, acc.w);
        acc.x = fmaf(k3, v3.x, acc.x); acc.y = fmaf(k3, v3.y, acc.y);
        acc.z = fmaf(k3, v3.z, acc.z); acc.w = fmaf(k3, v3.w, acc.w);
    }
    for (; j < end; j++) {
        int2 e = g_edge[j];
        float kk = __int_as_float(e.y);
        float4 vv = Bv[(size_t)e.x * LPN + c];
        acc.x = fmaf(kk, vv.x, acc.x); acc.y = fmaf(kk, vv.y, acc.y);
        acc.z = fmaf(kk, vv.z, acc.z); acc.w = fmaf(kk, vv.w, acc.w);
    }

    // BN: val = acc*scale + (be - m*scale)
    float sx = g[c0 + 0] * rsqrtf(v[c0 + 0] + EPSV);
    float sy = g[c0 + 1] * rsqrtf(v[c0 + 1] + EPSV);
    float sz = g[c0 + 2] * rsqrtf(v[c0 + 2] + EPSV);
    float sw = g[c0 + 3] * rsqrtf(v[c0 + 3] + EPSV);
    float4 val;
    val.x = fmaf(acc.x, sx, fmaf(-m[c0 + 0], sx, be[c0 + 0]));
    val.y = fmaf(acc.y, sy, fmaf(-m[c0 + 1], sy, be[c0 + 1]));
    val.z = fmaf(acc.z, sz, fmaf(-m[c0 + 2], sz, be[c0 + 2]));
    val.w = fmaf(acc.w, sw, fmaf(-m[c0 + 3], sw, be[c0 + 3]));

    if (FINAL) {
        *reinterpret_cast<float4*>(&out[(size_t)node * DO + c0]) = val;
    } else {
        float4* Ap = reinterpret_cast<float4*>(&g_bufA[(size_t)node * HDIM + c0]);
        float4 old = *Ap;
        val.x = fmaxf(val.x, 0.0f) + old.x;
        val.y = fmaxf(val.y, 0.0f) + old.y;
        val.z = fmaxf(val.z, 0.0f) + old.z;
        val.w = fmaxf(val.w, 0.0f) + old.w;
        *Ap = val;
    }
}

// ---------------------------------------------------------------------------
extern "C" void kernel_launch(void* const* d_in, const int* in_sizes, int n_in,
                              void* d_out, int out_size) {
    const float* x    = (const float*)d_in[0];
    const int*   ei   = (const int*)d_in[1];      // int32 edge_index [2,E]
    const float* W_in = (const float*)d_in[2];
    const float* b_in = (const float*)d_in[3];

    const float* W0  = (const float*)d_in[4];
    const float* b0  = (const float*)d_in[5];
    const float* g0  = (const float*)d_in[6];
    const float* be0 = (const float*)d_in[7];
    const float* m0  = (const float*)d_in[8];
    const float* v0  = (const float*)d_in[9];

    const float* W1  = (const float*)d_in[10];
    const float* b1  = (const float*)d_in[11];
    const float* g1  = (const float*)d_in[12];
    const float* be1 = (const float*)d_in[13];
    const float* m1  = (const float*)d_in[14];
    const float* v1  = (const float*)d_in[15];

    const float* W2  = (const float*)d_in[16];
    const float* b2  = (const float*)d_in[17];
    const float* g2  = (const float*)d_in[18];
    const float* be2 = (const float*)d_in[19];
    const float* m2  = (const float*)d_in[20];
    const float* v2  = (const float*)d_in[21];

    int N_ = in_sizes[0] / FDIM;
    int E_ = in_sizes[1] / 2;
    float* out = (float*)d_out;

    const int T = 256;

    // ---- CSR build (int atomics only) ----
    zero_rowptr_kernel<<<(N_ + 1 + T - 1) / T, T>>>(N_ + 1);
    hist_kernel<<<(E_ + T - 1) / T, T>>>(ei, E_);
    scan_kernel<<<1, 1024>>>(N_ + 1);
    dinv_fill_kernel<<<(N_ + T - 1) / T, T>>>(N_);
    scatter_kernel<<<(E_ + T - 1) / T, T>>>(ei, E_);

    // ---- input projection ----
    inproj_kernel<<<((size_t)N_ * HDIM + T - 1) / T, T>>>(x, W_in, b_in, N_);

    int gemm_blocks = (N_ + 63) / 64;
    int gat128_blocks = (int)(((size_t)N_ * (HDIM / 4) + T - 1) / T);
    int gat64_blocks  = (int)(((size_t)N_ * (DDIM / 4) + T - 1) / T);

    // ---- layer 0 (128 -> 128) ----
    gemm_kernel<HDIM><<<gemm_blocks, 256>>>(W0, N_);
    gather_kernel<HDIM, false><<<gat128_blocks, T>>>(b0, g0, be0, m0, v0, nullptr, N_);

    // ---- layer 1 (128 -> 128) ----
    gemm_kernel<HDIM><<<gemm_blocks, 256>>>(W1, N_);
    gather_kernel<HDIM, false><<<gat128_blocks, T>>>(b1, g1, be1, m1, v1, nullptr, N_);

    // ---- layer 2 (128 -> 64), BN only ----
    gemm_kernel<DDIM><<<gemm_blocks, 256>>>(W2, N_);
    gather_kernel<DDIM, true><<<gat64_blocks, T>>>(b2, g2, be2, m2, v2, out, N_);
}

// round 15
// speedup vs baseline: 1.5726x; 1.5726x over previous
#include <cuda_runtime.h>
#include <cuda_fp16.h>
#include <cstdint>

// Problem constants
#define MAXN 100000
#define MAXE 3200000
#define FDIM 7
#define HDIM 128
#define DDIM 64
#define EPSV 1e-5f

// Scratch (__device__ globals; allocation-free rule)
__device__ float  g_bufA[MAXN * HDIM];   // running node features h [N,128] (fp32)
__device__ __half g_bufBh[MAXN * HDIM];  // h @ W as fp16 (stride = DO of layer)
__device__ float  g_dinv[MAXN];
__device__ int    g_rowptr[MAXN + 1];    // CSR row pointers over dst
__device__ int    g_fill[MAXN];          // scatter cursors
__device__ int    g_srcidx[MAXE];        // CSR: src node per incoming edge
__device__ float  g_coef[MAXE];          // CSR: dinv[src]*dinv[dst] per edge

// ---------------------------------------------------------------------------
// CSR build  (edge_index is INT32: row 0 = src[0..E), row 1 = dst[0..E))
// ---------------------------------------------------------------------------
__global__ void zero_rowptr_kernel(int n1) {
    int i = blockIdx.x * blockDim.x + threadIdx.x;
    if (i < n1) g_rowptr[i] = 0;
}

__global__ void hist_kernel(const int* __restrict__ ei, int E_) {
    int e = blockIdx.x * blockDim.x + threadIdx.x;
    if (e < E_) {
        int dst = ei[E_ + e];
        atomicAdd(&g_rowptr[dst + 1], 1);   // INT atomic only
    }
}

// in-place inclusive scan over rowptr[0..n) — one block, 1024 threads
__global__ void scan_kernel(int n) {
    __shared__ int part[1024];
    int t = threadIdx.x;
    int C = (n + 1023) / 1024;
    int b = t * C;
    int e = b + C; if (e > n) e = n;
    int s = 0;
    for (int i = b; i < e; i++) s += g_rowptr[i];
    part[t] = s;
    __syncthreads();
    if (t == 0) {
        int run = 0;
        for (int i = 0; i < 1024; i++) { int x = part[i]; part[i] = run; run += x; }
    }
    __syncthreads();
    int run = part[t];
    for (int i = b; i < e; i++) { run += g_rowptr[i]; g_rowptr[i] = run; }
}

// dinv from degrees (+1 self-loop); also init fill cursors
__global__ void dinv_fill_kernel(int n) {
    int i = blockIdx.x * blockDim.x + threadIdx.x;
    if (i < n) {
        int beg = g_rowptr[i];
        int deg = g_rowptr[i + 1] - beg;
        g_dinv[i] = rsqrtf((float)deg + 1.0f);
        g_fill[i] = beg;
    }
}

__global__ void scatter_kernel(const int* __restrict__ ei, int E_) {
    int e = blockIdx.x * blockDim.x + threadIdx.x;
    if (e < E_) {
        int src = ei[e];
        int dst = ei[E_ + e];
        int pos = atomicAdd(&g_fill[dst], 1);   // INT atomic
        g_srcidx[pos] = src;
        g_coef[pos] = g_dinv[src] * g_dinv[dst];
    }
}

// ---------------------------------------------------------------------------
// input projection: bufA = relu(x @ W_in + b_in)   x:[N,7] W:[7,128]
// ---------------------------------------------------------------------------
__global__ void inproj_kernel(const float* __restrict__ x,
                              const float* __restrict__ W,
                              const float* __restrict__ b,
                              int n) {
    int i = blockIdx.x * blockDim.x + threadIdx.x;
    if (i >= n * HDIM) return;
    int node = i >> 7;
    int c = i & 127;
    float s = b[c];
#pragma unroll
    for (int k = 0; k < FDIM; k++)
        s = fmaf(x[node * FDIM + k], W[k * HDIM + c], s);
    g_bufA[i] = fmaxf(s, 0.0f);
}

// ---------------------------------------------------------------------------
// GEMM: bufBh = fp16(bufA @ W)   A:[n,128] fp32, W:[128,DO], out stride DO
// 64 rows x DO cols per block, 256 threads. (Round-8 scalar FFMA structure.)
// ---------------------------------------------------------------------------
template <int DO>
__global__ void gemm_kernel(const float* __restrict__ W, int n) {
    constexpr int DI = HDIM;
    constexpr int TM = 64;
    constexpr int CT = DO / 4;        // threads along columns (4 cols each)
    constexpr int RT = 256 / CT;      // threads along rows
    constexpr int RM = TM / RT;       // rows per thread
    constexpr int LDA = DI + 1;       // padded smem stride

    __shared__ float Asm[TM * LDA];

    int m0 = blockIdx.x * TM;
    int tid = threadIdx.x;

    for (int idx = tid; idx < TM * DI; idx += 256) {
        int r = idx >> 7;             // DI = 128
        int c = idx & 127;
        int gr = m0 + r;
        Asm[r * LDA + c] = (gr < n) ? g_bufA[(size_t)gr * DI + c] : 0.0f;
    }
    __syncthreads();

    int ct = tid % CT;
    int ry = tid / CT;
    int c0 = ct * 4;

    float acc[RM][4];
#pragma unroll
    for (int j = 0; j < RM; j++) {
        acc[j][0] = 0.f; acc[j][1] = 0.f; acc[j][2] = 0.f; acc[j][3] = 0.f;
    }

#pragma unroll 8
    for (int k = 0; k < DI; k++) {
        float4 wv = __ldg(reinterpret_cast<const float4*>(&W[k * DO + c0]));
#pragma unroll
        for (int j = 0; j < RM; j++) {
            float a = Asm[(ry + RT * j) * LDA + k];
            acc[j][0] = fmaf(a, wv.x, acc[j][0]);
            acc[j][1] = fmaf(a, wv.y, acc[j][1]);
            acc[j][2] = fmaf(a, wv.z, acc[j][2]);
            acc[j][3] = fmaf(a, wv.w, acc[j][3]);
        }
    }

#pragma unroll
    for (int j = 0; j < RM; j++) {
        int node = m0 + ry + RT * j;
        if (node < n) {
            __half2 p0 = __floats2half2_rn(acc[j][0], acc[j][1]);
            __half2 p1 = __floats2half2_rn(acc[j][2], acc[j][3]);
            uint2 o;
            o.x = *reinterpret_cast<const unsigned int*>(&p0);
            o.y = *reinterpret_cast<const unsigned int*>(&p1);
            *reinterpret_cast<uint2*>(&g_bufBh[(size_t)node * DO + c0]) = o;
        }
    }
}

// ---------------------------------------------------------------------------
// Fused gather: agg = sum_in coef*bufB[src] + bufB[node]*dinv^2 + bias,
// then BN (+relu+residual). bufB is fp16 (half the LTS bytes); accumulate fp32.
// One lane per (node, 4 cols). NO atomics, NO float reds.
// ---------------------------------------------------------------------------
__device__ __forceinline__ float4 loadB4(const __half* base, size_t node,
                                         int DOstride, int c0) {
    uint2 r = *reinterpret_cast<const uint2*>(&base[node * DOstride + c0]);
    __half2 h0 = *reinterpret_cast<const __half2*>(&r.x);
    __half2 h1 = *reinterpret_cast<const __half2*>(&r.y);
    float2 f0 = __half22float2(h0);
    float2 f1 = __half22float2(h1);
    return make_float4(f0.x, f0.y, f1.x, f1.y);
}

template <int DO, bool FINAL>
__global__ void gather_kernel(const float* __restrict__ bias,
                              const float* __restrict__ g,
                              const float* __restrict__ be,
                              const float* __restrict__ m,
                              const float* __restrict__ v,
                              float* __restrict__ out,
                              int n) {
    constexpr int LPN = DO / 4;       // lanes per node
    int gt = blockIdx.x * blockDim.x + threadIdx.x;
    int node = gt / LPN;
    int c = gt - node * LPN;
    if (node >= n) return;
    int c0 = c * 4;

    const __half* B = g_bufBh;

    float dv = g_dinv[node];
    float d2 = dv * dv;

    float4 hv = loadB4(B, (size_t)node, DO, c0);
    float4 acc;
    acc.x = fmaf(hv.x, d2, bias[c0 + 0]);
    acc.y = fmaf(hv.y, d2, bias[c0 + 1]);
    acc.z = fmaf(hv.z, d2, bias[c0 + 2]);
    acc.w = fmaf(hv.w, d2, bias[c0 + 3]);

    int j = g_rowptr[node];
    int end = g_rowptr[node + 1];

    // unroll-by-4 for MLP against L2 latency
    for (; j + 4 <= end; j += 4) {
        int s0 = g_srcidx[j + 0], s1 = g_srcidx[j + 1];
        int s2 = g_srcidx[j + 2], s3 = g_srcidx[j + 3];
        float k0 = g_coef[j + 0], k1 = g_coef[j + 1];
        float k2 = g_coef[j + 2], k3 = g_coef[j + 3];
        float4 v0 = loadB4(B, (size_t)s0, DO, c0);
        float4 v1 = loadB4(B, (size_t)s1, DO, c0);
        float4 v2 = loadB4(B, (size_t)s2, DO, c0);
        float4 v3 = loadB4(B, (size_t)s3, DO, c0);
        acc.x = fmaf(k0, v0.x, acc.x); acc.y = fmaf(k0, v0.y, acc.y);
        acc.z = fmaf(k0, v0.z, acc.z); acc.w = fmaf(k0, v0.w, acc.w);
        acc.x = fmaf(k1, v1.x, acc.x); acc.y = fmaf(k1, v1.y, acc.y);
        acc.z = fmaf(k1, v1.z, acc.z); acc.w = fmaf(k1, v1.w, acc.w);
        acc.x = fmaf(k2, v2.x, acc.x); acc.y = fmaf(k2, v2.y, acc.y);
        acc.z = fmaf(k2, v2.z, acc.z); acc.w = fmaf(k2, v2.w, acc.w);
        acc.x = fmaf(k3, v3.x, acc.x); acc.y = fmaf(k3, v3.y, acc.y);
        acc.z = fmaf(k3, v3.z, acc.z); acc.w = fmaf(k3, v3.w, acc.w);
    }
    for (; j < end; j++) {
        int s = g_srcidx[j];
        float kk = g_coef[j];
        float4 vv = loadB4(B, (size_t)s, DO, c0);
        acc.x = fmaf(kk, vv.x, acc.x); acc.y = fmaf(kk, vv.y, acc.y);
        acc.z = fmaf(kk, vv.z, acc.z); acc.w = fmaf(kk, vv.w, acc.w);
    }

    // BN: val = acc*scale + (be - m*scale)
    float sx = g[c0 + 0] * rsqrtf(v[c0 + 0] + EPSV);
    float sy = g[c0 + 1] * rsqrtf(v[c0 + 1] + EPSV);
    float sz = g[c0 + 2] * rsqrtf(v[c0 + 2] + EPSV);
    float sw = g[c0 + 3] * rsqrtf(v[c0 + 3] + EPSV);
    float4 val;
    val.x = fmaf(acc.x, sx, fmaf(-m[c0 + 0], sx, be[c0 + 0]));
    val.y = fmaf(acc.y, sy, fmaf(-m[c0 + 1], sy, be[c0 + 1]));
    val.z = fmaf(acc.z, sz, fmaf(-m[c0 + 2], sz, be[c0 + 2]));
    val.w = fmaf(acc.w, sw, fmaf(-m[c0 + 3], sw, be[c0 + 3]));

    if (FINAL) {
        *reinterpret_cast<float4*>(&out[(size_t)node * DO + c0]) = val;
    } else {
        float4* Ap = reinterpret_cast<float4*>(&g_bufA[(size_t)node * HDIM + c0]);
        float4 old = *Ap;
        val.x = fmaxf(val.x, 0.0f) + old.x;
        val.y = fmaxf(val.y, 0.0f) + old.y;
        val.z = fmaxf(val.z, 0.0f) + old.z;
        val.w = fmaxf(val.w, 0.0f) + old.w;
        *Ap = val;
    }
}

// ---------------------------------------------------------------------------
extern "C" void kernel_launch(void* const* d_in, const int* in_sizes, int n_in,
                              void* d_out, int out_size) {
    const float* x    = (const float*)d_in[0];
    const int*   ei   = (const int*)d_in[1];      // int32 edge_index [2,E]
    const float* W_in = (const float*)d_in[2];
    const float* b_in = (const float*)d_in[3];

    const float* W0  = (const float*)d_in[4];
    const float* b0  = (const float*)d_in[5];
    const float* g0  = (const float*)d_in[6];
    const float* be0 = (const float*)d_in[7];
    const float* m0  = (const float*)d_in[8];
    const float* v0  = (const float*)d_in[9];

    const float* W1  = (const float*)d_in[10];
    const float* b1  = (const float*)d_in[11];
    const float* g1  = (const float*)d_in[12];
    const float* be1 = (const float*)d_in[13];
    const float* m1  = (const float*)d_in[14];
    const float* v1  = (const float*)d_in[15];

    const float* W2  = (const float*)d_in[16];
    const float* b2  = (const float*)d_in[17];
    const float* g2  = (const float*)d_in[18];
    const float* be2 = (const float*)d_in[19];
    const float* m2  = (const float*)d_in[20];
    const float* v2  = (const float*)d_in[21];

    int N_ = in_sizes[0] / FDIM;
    int E_ = in_sizes[1] / 2;
    float* out = (float*)d_out;

    const int T = 256;

    // ---- CSR build (int atomics only) ----
    zero_rowptr_kernel<<<(N_ + 1 + T - 1) / T, T>>>(N_ + 1);
    hist_kernel<<<(E_ + T - 1) / T, T>>>(ei, E_);
    scan_kernel<<<1, 1024>>>(N_ + 1);
    dinv_fill_kernel<<<(N_ + T - 1) / T, T>>>(N_);
    scatter_kernel<<<(E_ + T - 1) / T, T>>>(ei, E_);

    // ---- input projection ----
    inproj_kernel<<<((size_t)N_ * HDIM + T - 1) / T, T>>>(x, W_in, b_in, N_);

    int gemm_blocks = (N_ + 63) / 64;
    int gat128_blocks = (int)(((size_t)N_ * (HDIM / 4) + T - 1) / T);
    int gat64_blocks  = (int)(((size_t)N_ * (DDIM / 4) + T - 1) / T);

    // ---- layer 0 (128 -> 128) ----
    gemm_kernel<HDIM><<<gemm_blocks, 256>>>(W0, N_);
    gather_kernel<HDIM, false><<<gat128_blocks, T>>>(b0, g0, be0, m0, v0, nullptr, N_);

    // ---- layer 1 (128 -> 128) ----
    gemm_kernel<HDIM><<<gemm_blocks, 256>>>(W1, N_);
    gather_kernel<HDIM, false><<<gat128_blocks, T>>>(b1, g1, be1, m1, v1, nullptr, N_);

    // ---- layer 2 (128 -> 64), BN only ----
    gemm_kernel<DDIM><<<gemm_blocks, 256>>>(W2, N_);
    gather_kernel<DDIM, true><<<gat64_blocks, T>>>(b2, g2, be2, m2, v2, out, N_);
}

// round 17
// speedup vs baseline: 2.0959x; 1.3328x over previous
#include <cuda_runtime.h>
#include <cuda_fp16.h>
#include <cstdint>

// Problem constants
#define MAXN 100000
#define MAXE 3200000
#define FDIM 7
#define HDIM 128
#define DDIM 64
#define EPSV 1e-5f

// Scratch (__device__ globals; allocation-free rule)
__device__ float  g_bufA[MAXN * HDIM];   // running node features h [N,128] (fp32, residual)
__device__ __half g_bufAh[MAXN * HDIM];  // fp16 mirror of bufA (GEMM input)
__device__ __half g_bufBh[MAXN * HDIM];  // h @ W as fp16 (stride = DO of layer)
__device__ __half g_Wh[HDIM * HDIM];     // current layer W in fp16
__device__ float  g_dinv[MAXN];
__device__ int    g_rowptr[MAXN + 1];    // CSR row pointers over dst
__device__ int    g_fill[MAXN];          // scatter cursors
__device__ int    g_srcidx[MAXE];        // CSR: src node per incoming edge
__device__ float  g_coef[MAXE];          // CSR: dinv[src]*dinv[dst] per edge

__device__ __forceinline__ unsigned sptr(const void* p) {
    return (unsigned)__cvta_generic_to_shared(p);
}

// ---------------------------------------------------------------------------
// CSR build  (edge_index is INT32: row 0 = src[0..E), row 1 = dst[0..E))
// ---------------------------------------------------------------------------
__global__ void zero_rowptr_kernel(int n1) {
    int i = blockIdx.x * blockDim.x + threadIdx.x;
    if (i < n1) g_rowptr[i] = 0;
}

__global__ void hist_kernel(const int* __restrict__ ei, int E_) {
    int e = blockIdx.x * blockDim.x + threadIdx.x;
    if (e < E_) {
        int dst = ei[E_ + e];
        atomicAdd(&g_rowptr[dst + 1], 1);   // INT atomic only
    }
}

// in-place inclusive scan over rowptr[0..n) — one block, 1024 threads
__global__ void scan_kernel(int n) {
    __shared__ int part[1024];
    int t = threadIdx.x;
    int C = (n + 1023) / 1024;
    int b = t * C;
    int e = b + C; if (e > n) e = n;
    int s = 0;
    for (int i = b; i < e; i++) s += g_rowptr[i];
    part[t] = s;
    __syncthreads();
    if (t == 0) {
        int run = 0;
        for (int i = 0; i < 1024; i++) { int x = part[i]; part[i] = run; run += x; }
    }
    __syncthreads();
    int run = part[t];
    for (int i = b; i < e; i++) { run += g_rowptr[i]; g_rowptr[i] = run; }
}

__global__ void dinv_fill_kernel(int n) {
    int i = blockIdx.x * blockDim.x + threadIdx.x;
    if (i < n) {
        int beg = g_rowptr[i];
        int deg = g_rowptr[i + 1] - beg;
        g_dinv[i] = rsqrtf((float)deg + 1.0f);
        g_fill[i] = beg;
    }
}

__global__ void scatter_kernel(const int* __restrict__ ei, int E_) {
    int e = blockIdx.x * blockDim.x + threadIdx.x;
    if (e < E_) {
        int src = ei[e];
        int dst = ei[E_ + e];
        int pos = atomicAdd(&g_fill[dst], 1);   // INT atomic
        g_srcidx[pos] = src;
        g_coef[pos] = g_dinv[src] * g_dinv[dst];
    }
}

// ---------------------------------------------------------------------------
// W fp32 -> fp16 conversion (per layer)
// ---------------------------------------------------------------------------
__global__ void convW_kernel(const float* __restrict__ W, int sz) {
    int i = blockIdx.x * blockDim.x + threadIdx.x;
    if (i < sz) g_Wh[i] = __float2half_rn(W[i]);
}

// ---------------------------------------------------------------------------
// input projection: bufA/bufAh = relu(x @ W_in + b_in)   x:[N,7] W:[7,128]
// ---------------------------------------------------------------------------
__global__ void inproj_kernel(const float* __restrict__ x,
                              const float* __restrict__ W,
                              const float* __restrict__ b,
                              int n) {
    int i = blockIdx.x * blockDim.x + threadIdx.x;
    if (i >= n * HDIM) return;
    int node = i >> 7;
    int c = i & 127;
    float s = b[c];
#pragma unroll
    for (int k = 0; k < FDIM; k++)
        s = fmaf(x[node * FDIM + k], W[k * HDIM + c], s);
    float r = fmaxf(s, 0.0f);
    g_bufA[i] = r;
    g_bufAh[i] = __float2half_rn(r);
}

// ---------------------------------------------------------------------------
// Tensor-core GEMM: bufBh = fp16(bufAh @ Wh)
// A:[n,128] fp16, W:[128,DO] fp16, fp32 accum (mma.sync.m16n8k16).
// Block tile 64 x DO, 8 warps (256 thr). XOR-swizzled smem, ldmatrix.
// ---------------------------------------------------------------------------
template <int DO>
__global__ void gemm_mma_kernel(int n) {
    constexpr int DI = HDIM;           // 128
    constexpr int TM = 64;
    constexpr int CHA = DI / 8;        // 16 8-half chunks per A row
    constexpr int CHW = DO / 8;        // chunks per W row
    constexpr int NTW = DO / 16;       // 8-wide n-tiles per warp (DO/2/8)

    __shared__ __half Asm[TM * DI];    // 16 KB
    __shared__ __half Wsm[DI * DO];    // 32 KB (DO=128) / 16 KB (DO=64)

    int tid = threadIdx.x;
    int m0 = blockIdx.x * TM;

    // A tile, swizzled chunk layout: chunk ch of row r stored at ch ^ (r&7)
    for (int idx = tid; idx < TM * CHA; idx += 256) {
        int r = idx / CHA, ch = idx % CHA;
        uint4 val = make_uint4(0, 0, 0, 0);
        int gr = m0 + r;
        if (gr < n) val = *reinterpret_cast<const uint4*>(&g_bufAh[(size_t)gr * DI + ch * 8]);
        *reinterpret_cast<uint4*>(&Asm[r * DI + (ch ^ (r & 7)) * 8]) = val;
    }
    // W tile, same swizzle
    for (int idx = tid; idx < DI * CHW; idx += 256) {
        int r = idx / CHW, ch = idx % CHW;
        uint4 val = *reinterpret_cast<const uint4*>(&g_Wh[r * DO + ch * 8]);
        *reinterpret_cast<uint4*>(&Wsm[r * DO + (ch ^ (r & 7)) * 8]) = val;
    }
    __syncthreads();

    int wid = tid >> 5, lane = tid & 31;
    int wm = wid & 3;                  // 4 m-tiles of 16 rows
    int wn = wid >> 2;                 // 2 n-halves
    int nbase = wn * (DO / 2);

    float acc[NTW][4];
#pragma unroll
    for (int t = 0; t < NTW; t++) { acc[t][0] = acc[t][1] = acc[t][2] = acc[t][3] = 0.f; }

#pragma unroll
    for (int ki = 0; ki < DI / 16; ki++) {
        unsigned a0, a1, a2, a3;
        {
            int rr = wm * 16 + (lane & 15);
            int ck = (2 * ki + (lane >> 4)) ^ (rr & 7);
            unsigned addr = sptr(&Asm[rr * DI + ck * 8]);
            asm volatile("ldmatrix.sync.aligned.m8n8.x4.shared.b16 {%0,%1,%2,%3}, [%4];"
                         : "=r"(a0), "=r"(a1), "=r"(a2), "=r"(a3) : "r"(addr));
        }
#pragma unroll
        for (int p = 0; p < NTW / 2; p++) {
            unsigned b0, b1, b2, b3;
            int grp = lane >> 3;
            int rr = ki * 16 + (grp & 1) * 8 + (lane & 7);
            int cn = ((nbase >> 3) + p * 2 + (grp >> 1)) ^ (rr & 7);
            unsigned addr = sptr(&Wsm[rr * DO + cn * 8]);
            asm volatile("ldmatrix.sync.aligned.m8n8.x4.trans.shared.b16 {%0,%1,%2,%3}, [%4];"
                         : "=r"(b0), "=r"(b1), "=r"(b2), "=r"(b3) : "r"(addr));
            asm volatile("mma.sync.aligned.m16n8k16.row.col.f32.f16.f16.f32 "
                         "{%0,%1,%2,%3}, {%4,%5,%6,%7}, {%8,%9}, {%0,%1,%2,%3};"
                         : "+f"(acc[2*p][0]), "+f"(acc[2*p][1]), "+f"(acc[2*p][2]), "+f"(acc[2*p][3])
                         : "r"(a0), "r"(a1), "r"(a2), "r"(a3), "r"(b0), "r"(b1));
            asm volatile("mma.sync.aligned.m16n8k16.row.col.f32.f16.f16.f32 "
                         "{%0,%1,%2,%3}, {%4,%5,%6,%7}, {%8,%9}, {%0,%1,%2,%3};"
                         : "+f"(acc[2*p+1][0]), "+f"(acc[2*p+1][1]), "+f"(acc[2*p+1][2]), "+f"(acc[2*p+1][3])
                         : "r"(a0), "r"(a1), "r"(a2), "r"(a3), "r"(b2), "r"(b3));
        }
    }

    // epilogue: thread owns (r0, col..col+1) and (r0+8, col..col+1) per n-tile
    int r0 = m0 + wm * 16 + (lane >> 2);
    int cb = nbase + (lane & 3) * 2;
#pragma unroll
    for (int t = 0; t < NTW; t++) {
        int col = cb + t * 8;
        __half2 lo = __floats2half2_rn(acc[t][0], acc[t][1]);
        __half2 hi = __floats2half2_rn(acc[t][2], acc[t][3]);
        if (r0 < n)
            *reinterpret_cast<__half2*>(&g_bufBh[(size_t)r0 * DO + col]) = lo;
        if (r0 + 8 < n)
            *reinterpret_cast<__half2*>(&g_bufBh[(size_t)(r0 + 8) * DO + col]) = hi;
    }
}

// ---------------------------------------------------------------------------
// Fused gather: agg = sum_in coef*bufB[src] + bufB[node]*dinv^2 + bias,
// then BN (+relu+residual). bufB fp16, accumulate fp32. One lane/(node,4cols).
// ---------------------------------------------------------------------------
__device__ __forceinline__ float4 loadB4(const __half* base, size_t node,
                                         int DOstride, int c0) {
    uint2 r = *reinterpret_cast<const uint2*>(&base[node * DOstride + c0]);
    __half2 h0 = *reinterpret_cast<const __half2*>(&r.x);
    __half2 h1 = *reinterpret_cast<const __half2*>(&r.y);
    float2 f0 = __half22float2(h0);
    float2 f1 = __half22float2(h1);
    return make_float4(f0.x, f0.y, f1.x, f1.y);
}

template <int DO, bool FINAL>
__global__ void gather_kernel(const float* __restrict__ bias,
                              const float* __restrict__ g,
                              const float* __restrict__ be,
                              const float* __restrict__ m,
                              const float* __restrict__ v,
                              float* __restrict__ out,
                              int n) {
    constexpr int LPN = DO / 4;       // lanes per node
    int gt = blockIdx.x * blockDim.x + threadIdx.x;
    int node = gt / LPN;
    int c = gt - node * LPN;
    if (node >= n) return;
    int c0 = c * 4;

    const __half* B = g_bufBh;

    float dv = g_dinv[node];
    float d2 = dv * dv;

    float4 hv = loadB4(B, (size_t)node, DO, c0);
    float4 acc;
    acc.x = fmaf(hv.x, d2, bias[c0 + 0]);
    acc.y = fmaf(hv.y, d2, bias[c0 + 1]);
    acc.z = fmaf(hv.z, d2, bias[c0 + 2]);
    acc.w = fmaf(hv.w, d2, bias[c0 + 3]);

    int j = g_rowptr[node];
    int end = g_rowptr[node + 1];

    for (; j + 4 <= end; j += 4) {
        int s0 = g_srcidx[j + 0], s1 = g_srcidx[j + 1];
        int s2 = g_srcidx[j + 2], s3 = g_srcidx[j + 3];
        float k0 = g_coef[j + 0], k1 = g_coef[j + 1];
        float k2 = g_coef[j + 2], k3 = g_coef[j + 3];
        float4 v0 = loadB4(B, (size_t)s0, DO, c0);
        float4 v1 = loadB4(B, (size_t)s1, DO, c0);
        float4 v2 = loadB4(B, (size_t)s2, DO, c0);
        float4 v3 = loadB4(B, (size_t)s3, DO, c0);
        acc.x = fmaf(k0, v0.x, acc.x); acc.y = fmaf(k0, v0.y, acc.y);
        acc.z = fmaf(k0, v0.z, acc.z); acc.w = fmaf(k0, v0.w, acc.w);
        acc.x = fmaf(k1, v1.x, acc.x); acc.y = fmaf(k1, v1.y, acc.y);
        acc.z = fmaf(k1, v1.z, acc.z); acc.w = fmaf(k1, v1.w, acc.w);
        acc.x = fmaf(k2, v2.x, acc.x); acc.y = fmaf(k2, v2.y, acc.y);
        acc.z = fmaf(k2, v2.z, acc.z); acc.w = fmaf(k2, v2.w, acc.w);
        acc.x = fmaf(k3, v3.x, acc.x); acc.y = fmaf(k3, v3.y, acc.y);
        acc.z = fmaf(k3, v3.z, acc.z); acc.w = fmaf(k3, v3.w, acc.w);
    }
    for (; j < end; j++) {
        int s = g_srcidx[j];
        float kk = g_coef[j];
        float4 vv = loadB4(B, (size_t)s, DO, c0);
        acc.x = fmaf(kk, vv.x, acc.x); acc.y = fmaf(kk, vv.y, acc.y);
        acc.z = fmaf(kk, vv.z, acc.z); acc.w = fmaf(kk, vv.w, acc.w);
    }

    // BN: val = acc*scale + (be - m*scale)
    float sx = g[c0 + 0] * rsqrtf(v[c0 + 0] + EPSV);
    float sy = g[c0 + 1] * rsqrtf(v[c0 + 1] + EPSV);
    float sz = g[c0 + 2] * rsqrtf(v[c0 + 2] + EPSV);
    float sw = g[c0 + 3] * rsqrtf(v[c0 + 3] + EPSV);
    float4 val;
    val.x = fmaf(acc.x, sx, fmaf(-m[c0 + 0], sx, be[c0 + 0]));
    val.y = fmaf(acc.y, sy, fmaf(-m[c0 + 1], sy, be[c0 + 1]));
    val.z = fmaf(acc.z, sz, fmaf(-m[c0 + 2], sz, be[c0 + 2]));
    val.w = fmaf(acc.w, sw, fmaf(-m[c0 + 3], sw, be[c0 + 3]));

    if (FINAL) {
        *reinterpret_cast<float4*>(&out[(size_t)node * DO + c0]) = val;
    } else {
        float4* Ap = reinterpret_cast<float4*>(&g_bufA[(size_t)node * HDIM + c0]);
        float4 old = *Ap;
        val.x = fmaxf(val.x, 0.0f) + old.x;
        val.y = fmaxf(val.y, 0.0f) + old.y;
        val.z = fmaxf(val.z, 0.0f) + old.z;
        val.w = fmaxf(val.w, 0.0f) + old.w;
        *Ap = val;
        // fp16 mirror for next layer's tensor-core GEMM
        __half2 p0 = __floats2half2_rn(val.x, val.y);
        __half2 p1 = __floats2half2_rn(val.z, val.w);
        uint2 o;
        o.x = *reinterpret_cast<const unsigned int*>(&p0);
        o.y = *reinterpret_cast<const unsigned int*>(&p1);
        *reinterpret_cast<uint2*>(&g_bufAh[(size_t)node * HDIM + c0]) = o;
    }
}

// ---------------------------------------------------------------------------
extern "C" void kernel_launch(void* const* d_in, const int* in_sizes, int n_in,
                              void* d_out, int out_size) {
    const float* x    = (const float*)d_in[0];
    const int*   ei   = (const int*)d_in[1];      // int32 edge_index [2,E]
    const float* W_in = (const float*)d_in[2];
    const float* b_in = (const float*)d_in[3];

    const float* W0  = (const float*)d_in[4];
    const float* b0  = (const float*)d_in[5];
    const float* g0  = (const float*)d_in[6];
    const float* be0 = (const float*)d_in[7];
    const float* m0  = (const float*)d_in[8];
    const float* v0  = (const float*)d_in[9];

    const float* W1  = (const float*)d_in[10];
    const float* b1  = (const float*)d_in[11];
    const float* g1  = (const float*)d_in[12];
    const float* be1 = (const float*)d_in[13];
    const float* m1  = (const float*)d_in[14];
    const float* v1  = (const float*)d_in[15];

    const float* W2  = (const float*)d_in[16];
    const float* b2  = (const float*)d_in[17];
    const float* g2  = (const float*)d_in[18];
    const float* be2 = (const float*)d_in[19];
    const float* m2  = (const float*)d_in[20];
    const float* v2  = (const float*)d_in[21];

    int N_ = in_sizes[0] / FDIM;
    int E_ = in_sizes[1] / 2;
    float* out = (float*)d_out;

    const int T = 256;

    // ---- CSR build (int atomics only) ----
    zero_rowptr_kernel<<<(N_ + 1 + T - 1) / T, T>>>(N_ + 1);
    hist_kernel<<<(E_ + T - 1) / T, T>>>(ei, E_);
    scan_kernel<<<1, 1024>>>(N_ + 1);
    dinv_fill_kernel<<<(N_ + T - 1) / T, T>>>(N_);
    scatter_kernel<<<(E_ + T - 1) / T, T>>>(ei, E_);

    // ---- input projection ----
    inproj_kernel<<<((size_t)N_ * HDIM + T - 1) / T, T>>>(x, W_in, b_in, N_);

    int gemm_blocks = (N_ + 63) / 64;
    int gat128_blocks = (int)(((size_t)N_ * (HDIM / 4) + T - 1) / T);
    int gat64_blocks  = (int)(((size_t)N_ * (DDIM / 4) + T - 1) / T);

    // ---- layer 0 (128 -> 128) ----
    convW_kernel<<<(HDIM * HDIM + T - 1) / T, T>>>(W0, HDIM * HDIM);
    gemm_mma_kernel<HDIM><<<gemm_blocks, 256>>>(N_);
    gather_kernel<HDIM, false><<<gat128_blocks, T>>>(b0, g0, be0, m0, v0, nullptr, N_);

    // ---- layer 1 (128 -> 128) ----
    convW_kernel<<<(HDIM * HDIM + T - 1) / T, T>>>(W1, HDIM * HDIM);
    gemm_mma_kernel<HDIM><<<gemm_blocks, 256>>>(N_);
    gather_kernel<HDIM, false><<<gat128_blocks, T>>>(b1, g1, be1, m1, v1, nullptr, N_);

    // ---- layer 2 (128 -> 64), BN only ----
    convW_kernel<<<(HDIM * DDIM + T - 1) / T, T>>>(W2, HDIM * DDIM);
    gemm_mma_kernel<DDIM><<<gemm_blocks, 256>>>(N_);
    gather_kernel<DDIM, true><<<gat64_blocks, T>>>(b2, g2, be2, m2, v2, out, N_);
}